// round 2
// baseline (speedup 1.0000x reference)
#include <cuda_runtime.h>

#define HID 64
#define MAX_NODES 100000
#define MAX_EDGES 2000000
#define TE 96   // edges per block tile

// Scratch: per-node hidden H, and precomputed P = H@A + be1, Q = H@B
__device__ float g_H[MAX_NODES * HID];
__device__ float g_P[MAX_NODES * HID];
__device__ float g_Q[MAX_NODES * HID];
__device__ int   g_U[MAX_EDGES];
__device__ int   g_V[MAX_EDGES];
__device__ int   g_is64;

// ---------------------------------------------------------------------------
// Kernel 0a: detect whether `pairs` is int64 or int32.
// Only reads the first 2*n_edges int32 words (in-bounds for BOTH dtypes).
// int64 case: odd words are high halves of values in [0,1e5) -> all zero.
// int32 case: odd words are random node indices -> some nonzero (certain).
// ---------------------------------------------------------------------------
__global__ void detect_kernel(const int* __restrict__ w, int n_edges) {
    __shared__ int any_nz;
    if (threadIdx.x == 0) any_nz = 0;
    __syncthreads();
    int nz = 0;
    // sample odd positions across the guaranteed-valid range [0, 2*n_edges)
    for (int j = threadIdx.x; j < 4096; j += blockDim.x) {
        long long idx = 1 + 2 * ((long long)j * (n_edges - 1) / 4096);
        if (idx < 2LL * n_edges) nz |= w[idx];
    }
    if (nz) atomicOr(&any_nz, 1);
    __syncthreads();
    if (threadIdx.x == 0) g_is64 = (any_nz == 0) ? 1 : 0;
}

// ---------------------------------------------------------------------------
// Kernel 0b: decode pairs -> g_U, g_V (int32), either dtype.
// ---------------------------------------------------------------------------
__global__ void decode_kernel(const int* __restrict__ w, int n_edges) {
    int is64 = g_is64;
    int e = blockIdx.x * blockDim.x + threadIdx.x;
    if (e >= n_edges) return;
    int u, v;
    if (is64) {
        u = w[4LL * e];       // low word of pairs[e][0]
        v = w[4LL * e + 2];   // low word of pairs[e][1]
    } else {
        u = w[2LL * e];
        v = w[2LL * e + 1];
    }
    g_U[e] = u;
    g_V[e] = v;
}

// ---------------------------------------------------------------------------
// Kernel 1: H = relu(relu(X @ W1 + b1) @ W2 + b2)
// 256 threads = 4 subgroups of 64; each subgroup handles one node.
// ---------------------------------------------------------------------------
__global__ void node_mlp_kernel(const float* __restrict__ X,
                                const float* __restrict__ W1,
                                const float* __restrict__ b1,
                                const float* __restrict__ W2,
                                const float* __restrict__ b2,
                                int n_nodes) {
    __shared__ float sW2[HID * HID];
    __shared__ float sh1[4][HID];

    int tid = threadIdx.x;
    for (int i = tid; i < HID * HID; i += 256) sW2[i] = W2[i];
    __syncthreads();

    int sub = tid >> 6;
    int t   = tid & 63;

    float w10 = W1[t], w11 = W1[64 + t], w12 = W1[128 + t], w13 = W1[192 + t];
    float bb1 = b1[t], bb2 = b2[t];

    for (int base = blockIdx.x * 4; base < n_nodes; base += gridDim.x * 4) {
        int node = base + sub;
        bool valid = node < n_nodes;
        float h1 = 0.f;
        if (valid) {
            float x0 = X[node * 4 + 0];
            float x1 = X[node * 4 + 1];
            float x2 = X[node * 4 + 2];
            float x3 = X[node * 4 + 3];
            h1 = bb1;
            h1 = fmaf(x0, w10, h1);
            h1 = fmaf(x1, w11, h1);
            h1 = fmaf(x2, w12, h1);
            h1 = fmaf(x3, w13, h1);
            h1 = fmaxf(h1, 0.f);
        }
        sh1[sub][t] = h1;
        __syncthreads();
        if (valid) {
            float acc = bb2;
            #pragma unroll 16
            for (int k = 0; k < HID; k++)
                acc = fmaf(sh1[sub][k], sW2[k * HID + t], acc);
            g_H[node * HID + t] = fmaxf(acc, 0.f);
        }
        __syncthreads();
    }
}

// ---------------------------------------------------------------------------
// Kernel 2: P = H @ A + be1 ; Q = H @ B   (A = We1 rows 0..63, B = rows 64..127)
// ---------------------------------------------------------------------------
__global__ void node_pq_kernel(const float* __restrict__ We1,
                               const float* __restrict__ be1,
                               int n_nodes) {
    __shared__ float sA[HID * HID];
    __shared__ float sB[HID * HID];
    __shared__ float sh[4][HID];

    int tid = threadIdx.x;
    for (int i = tid; i < HID * HID; i += 256) {
        sA[i] = We1[i];
        sB[i] = We1[HID * HID + i];
    }
    __syncthreads();

    int sub = tid >> 6;
    int t   = tid & 63;
    float bbe1 = be1[t];

    for (int base = blockIdx.x * 4; base < n_nodes; base += gridDim.x * 4) {
        int node = base + sub;
        bool valid = node < n_nodes;
        sh[sub][t] = valid ? g_H[node * HID + t] : 0.f;
        __syncthreads();
        if (valid) {
            float p = bbe1;
            float q = 0.f;
            #pragma unroll 16
            for (int k = 0; k < HID; k++) {
                float h = sh[sub][k];
                p = fmaf(h, sA[k * HID + t], p);
                q = fmaf(h, sB[k * HID + t], q);
            }
            g_P[node * HID + t] = p;
            g_Q[node * HID + t] = q;
        }
        __syncthreads();
    }
}

// ---------------------------------------------------------------------------
// Kernel 3: per edge e=(u,v):
//   acc[t] = P[u][t] + Q[v][t] + sum_k |H[u][k]-H[v][k]| * C[k][t]
//   score  = sum_t relu(acc[t]) * We2[t] + be2
// 96-edge tiles, 256 threads = 16 (dim groups of 4) x 16 (edge groups of 6).
// ---------------------------------------------------------------------------
__global__ void edge_kernel(const float* __restrict__ We1,
                            const float* __restrict__ We2,
                            const float* __restrict__ be2,
                            float* __restrict__ out,
                            int n_edges) {
    __shared__ float sD[TE][68];        // |hu-hv| tile, padded
    __shared__ float sC[HID * HID];     // C = We1 rows 128..191
    __shared__ int   su[TE], sv[TE];
    __shared__ float sW2v[HID];

    int tid = threadIdx.x;
    int e0  = blockIdx.x * TE;

    for (int i = tid; i < HID * HID; i += 256) sC[i] = We1[2 * HID * HID + i];
    if (tid < HID) sW2v[tid] = We2[tid];
    if (tid < TE) {
        int e = e0 + tid;
        su[tid] = (e < n_edges) ? g_U[e] : 0;
        sv[tid] = (e < n_edges) ? g_V[e] : 0;
    }
    __syncthreads();

    // Fill D tile: 96 edges x 16 float4 chunks (L2 gathers)
    #pragma unroll
    for (int j = tid; j < TE * 16; j += 256) {
        int e = j >> 4, c = j & 15;
        const float4 a = *(const float4*)&g_H[(size_t)su[e] * HID + 4 * c];
        const float4 b = *(const float4*)&g_H[(size_t)sv[e] * HID + 4 * c];
        sD[e][4 * c + 0] = fabsf(a.x - b.x);
        sD[e][4 * c + 1] = fabsf(a.y - b.y);
        sD[e][4 * c + 2] = fabsf(a.z - b.z);
        sD[e][4 * c + 3] = fabsf(a.w - b.w);
    }

    int tx = tid & 15;       // dim group: dims t0..t0+3
    int ty = tid >> 4;       // edge group: edges ty*6 .. ty*6+5
    int t0 = tx * 4;

    // Init accumulators with P[u] + Q[v] (be1 folded into P)
    float acc[6][4];
    #pragma unroll
    for (int i = 0; i < 6; i++) {
        int e = ty * 6 + i;
        const float4 p = *(const float4*)&g_P[(size_t)su[e] * HID + t0];
        const float4 q = *(const float4*)&g_Q[(size_t)sv[e] * HID + t0];
        acc[i][0] = p.x + q.x;
        acc[i][1] = p.y + q.y;
        acc[i][2] = p.z + q.z;
        acc[i][3] = p.w + q.w;
    }
    __syncthreads();

    // Mini-GEMM: acc[e][t] += D[e][k] * C[k][t]
    #pragma unroll 4
    for (int k = 0; k < HID; k++) {
        float4 c4 = *(const float4*)&sC[k * HID + t0];
        #pragma unroll
        for (int i = 0; i < 6; i++) {
            float d = sD[ty * 6 + i][k];
            acc[i][0] = fmaf(d, c4.x, acc[i][0]);
            acc[i][1] = fmaf(d, c4.y, acc[i][1]);
            acc[i][2] = fmaf(d, c4.z, acc[i][2]);
            acc[i][3] = fmaf(d, c4.w, acc[i][3]);
        }
    }

    // Epilogue: relu, dot with We2, reduce across 16 tx lanes (xor 1/2/4/8
    // stays within each 16-lane half of the warp).
    float w0 = sW2v[t0], w1 = sW2v[t0 + 1], w2 = sW2v[t0 + 2], w3 = sW2v[t0 + 3];
    float bias = be2[0];
    #pragma unroll
    for (int i = 0; i < 6; i++) {
        float s = fmaxf(acc[i][0], 0.f) * w0
                + fmaxf(acc[i][1], 0.f) * w1
                + fmaxf(acc[i][2], 0.f) * w2
                + fmaxf(acc[i][3], 0.f) * w3;
        s += __shfl_xor_sync(0xffffffffu, s, 1);
        s += __shfl_xor_sync(0xffffffffu, s, 2);
        s += __shfl_xor_sync(0xffffffffu, s, 4);
        s += __shfl_xor_sync(0xffffffffu, s, 8);
        if (tx == 0) {
            int e = e0 + ty * 6 + i;
            if (e < n_edges) out[e] = s + bias;
        }
    }
}

// ---------------------------------------------------------------------------
extern "C" void kernel_launch(void* const* d_in, const int* in_sizes, int n_in,
                              void* d_out, int out_size) {
    const float* X     = (const float*)d_in[0];
    const int*   pairs = (const int*)d_in[1];   // int32 OR int64; detected on-device
    const float* W1    = (const float*)d_in[2];
    const float* b1    = (const float*)d_in[3];
    const float* W2    = (const float*)d_in[4];
    const float* b2    = (const float*)d_in[5];
    const float* We1   = (const float*)d_in[6];
    const float* be1   = (const float*)d_in[7];
    const float* We2   = (const float*)d_in[8];
    const float* be2   = (const float*)d_in[9];
    float* out = (float*)d_out;

    int n_nodes = in_sizes[0] / 4;
    int n_edges = out_size;

    detect_kernel<<<1, 256>>>(pairs, n_edges);
    decode_kernel<<<(n_edges + 255) / 256, 256>>>(pairs, n_edges);
    node_mlp_kernel<<<1024, 256>>>(X, W1, b1, W2, b2, n_nodes);
    node_pq_kernel<<<1024, 256>>>(We1, be1, n_nodes);
    edge_kernel<<<(n_edges + TE - 1) / TE, 256>>>(We1, We2, be2, out, n_edges);
}